// round 7
// baseline (speedup 1.0000x reference)
#include <cuda_runtime.h>
#include <cuda_bf16.h>
#include <math.h>

#define BB 65536
#define KK 256
#define DD 128
#define NBLK 444
#define NITER 50

typedef unsigned long long u64;

// ---- scratch (static device globals; no allocation) ----
__device__ __nv_bfloat16 g_Kh[(size_t)BB * KK];  // K' in bf16 (32MB) — L2-resident
__device__ float g_ynT[DD * KK];         // normalized prototypes, k-major [k][j]
__device__ float g_xinv[BB];             // 1 / ||x_i||
__device__ float g_a[BB];                // exp(u)
__device__ float g_T[3][KK * 32];        // column sums, padded 128B apart
__device__ unsigned g_bar;               // grid barrier counter
__device__ double g_sum;

// 256-bit L2-pinned load of 16 bf16 -> 16 floats
__device__ __forceinline__ void ld256_bf16_el(const __nv_bfloat16* p, float* f) {
    u64 q[4];
    asm volatile("ld.global.L2::evict_last.v4.b64 {%0,%1,%2,%3}, [%4];"
                 : "=l"(q[0]), "=l"(q[1]), "=l"(q[2]), "=l"(q[3]) : "l"(p));
#pragma unroll
    for (int i = 0; i < 4; i++) {
        unsigned lo = (unsigned)(q[i] & 0xffffffffull);
        unsigned hi = (unsigned)(q[i] >> 32);
        float2 f0 = __bfloat1622float2(*(__nv_bfloat162*)&lo);
        float2 f1 = __bfloat1622float2(*(__nv_bfloat162*)&hi);
        f[i * 4 + 0] = f0.x; f[i * 4 + 1] = f0.y;
        f[i * 4 + 2] = f1.x; f[i * 4 + 3] = f1.y;
    }
}

// ---------------------------------------------------------------------------
__global__ void k_init(const float* __restrict__ proto) {
    int j = threadIdx.x;  // 0..255
    float ss = 0.f;
#pragma unroll 8
    for (int k = 0; k < DD; k++) { float v = proto[j * DD + k]; ss += v * v; }
    float inv = __fdividef(1.f, fmaxf(sqrtf(ss), 1e-12f));
    for (int k = 0; k < DD; k++) g_ynT[k * KK + j] = proto[j * DD + k] * inv;
    const float nuP = 1.f / (float)KK + 1e-8f;
    g_T[0][j * 32] = nuP;   // makes w == 1 on iteration 1 (v0 = 0)
    g_T[1][j * 32] = 0.f;   // accumulation target of iteration 1
    if (j == 0) { g_sum = 0.0; g_bar = 0u; }
}

// ---------------------------------------------------------------------------
__global__ void k_xnorm(const float* __restrict__ x) {
    int warp = threadIdx.x >> 5, lane = threadIdx.x & 31;
    int row = blockIdx.x * 8 + warp;
    float4 v = ((const float4*)(x + (size_t)row * DD))[lane];
    float ss = v.x * v.x + v.y * v.y + v.z * v.z + v.w * v.w;
#pragma unroll
    for (int o = 16; o; o >>= 1) ss += __shfl_xor_sync(0xffffffffu, ss, o);
    if (lane == 0) g_xinv[row] = __fdividef(1.f, fmaxf(sqrtf(ss), 1e-12f));
}

// ---------------------------------------------------------------------------
// cost GEMM: K' = exp(-10*(1 - xn.yn)) + 1e-8, stored bf16
// ---------------------------------------------------------------------------
__global__ void k_gemm(const float* __restrict__ x) {
    __shared__ float ys[32 * 256];  // k-chunk of prototypes [kk][col]  (32KB)
    __shared__ float xs[64 * 32];   // x tile [row][kk]                 (8KB)
    __shared__ float xrn[64];

    int t = threadIdx.x;
    int rowBase = blockIdx.x * 64;
    if (t < 64) xrn[t] = g_xinv[rowBase + t];

    int tx = t & 31, ty = t >> 5;
    float acc[8][8];
#pragma unroll
    for (int i = 0; i < 8; i++)
#pragma unroll
        for (int j = 0; j < 8; j++) acc[i][j] = 0.f;

    for (int kc = 0; kc < 4; kc++) {
        __syncthreads();
        {
            const float4* src = (const float4*)(g_ynT + kc * 32 * 256);
            float4* dst = (float4*)ys;
#pragma unroll
            for (int i = 0; i < 8; i++) dst[t + i * 256] = src[t + i * 256];
        }
        {
#pragma unroll
            for (int i = 0; i < 2; i++) {
                int idx = t + i * 256;
                int r = idx >> 3;
                int c4 = idx & 7;
                float4 v = *(const float4*)(x + (size_t)(rowBase + r) * DD + kc * 32 + c4 * 4);
                *(float4*)&xs[r * 32 + c4 * 4] = v;
            }
        }
        __syncthreads();
#pragma unroll 4
        for (int k = 0; k < 32; k++) {
            float4 b0 = *(const float4*)&ys[k * 256 + tx * 8];
            float4 b1 = *(const float4*)&ys[k * 256 + tx * 8 + 4];
#pragma unroll
            for (int i = 0; i < 8; i++) {
                float a = xs[(ty * 8 + i) * 32 + k];
                acc[i][0] += a * b0.x; acc[i][1] += a * b0.y;
                acc[i][2] += a * b0.z; acc[i][3] += a * b0.w;
                acc[i][4] += a * b1.x; acc[i][5] += a * b1.y;
                acc[i][6] += a * b1.z; acc[i][7] += a * b1.w;
            }
        }
    }

#pragma unroll
    for (int i = 0; i < 8; i++) {
        int row = rowBase + ty * 8 + i;
        float inv = xrn[ty * 8 + i];
        float kv[8];
#pragma unroll
        for (int j = 0; j < 8; j++) {
            float c = 1.f - acc[i][j] * inv;
            kv[j] = __expf(-10.f * c) + 1e-8f;
        }
        __nv_bfloat162 h0 = __float22bfloat162_rn(make_float2(kv[0], kv[1]));
        __nv_bfloat162 h1 = __float22bfloat162_rn(make_float2(kv[2], kv[3]));
        __nv_bfloat162 h2 = __float22bfloat162_rn(make_float2(kv[4], kv[5]));
        __nv_bfloat162 h3 = __float22bfloat162_rn(make_float2(kv[6], kv[7]));
        uint4 s;
        s.x = *(unsigned*)&h0; s.y = *(unsigned*)&h1;
        s.z = *(unsigned*)&h2; s.w = *(unsigned*)&h3;
        *(uint4*)&g_Kh[(size_t)row * KK + tx * 8] = s;
    }
}

// ---------------------------------------------------------------------------
// iteration helpers (bf16). Batch = 2 rows: lanes 0-15 -> row 2b, 16-31 -> 2b+1
// ---------------------------------------------------------------------------
__device__ __forceinline__ void iter_loadh(int b, int half, int hl, float* f) {
    const __nv_bfloat16* p = g_Kh + ((size_t)b * 2 + half) * KK + hl * 16;
    ld256_bf16_el(p, f);
}

__device__ __forceinline__ void iter_compute(int b, int half, int hl,
                                             const float* f, const float* w,
                                             float* tj, float muP) {
    float s = 0.f;
#pragma unroll
    for (int m = 0; m < 16; m++) s += f[m] * w[m];
#pragma unroll
    for (int o = 8; o; o >>= 1) s += __shfl_xor_sync(0xffffffffu, s, o);
    float a = muP * __fdividef(1.f, s);
    if (hl == 0) g_a[b * 2 + half] = a;
#pragma unroll
    for (int m = 0; m < 16; m++) tj[m] += f[m] * a;
}

// ---------------------------------------------------------------------------
// ALL 50 Sinkhorn iterations in one persistent kernel (grid = 444 resident
// blocks), separated by device-side grid barriers.
// ---------------------------------------------------------------------------
__global__ void __launch_bounds__(256, 3) k_sink() {
    const float nuP = 1.f / (float)KK + 1e-8f;
    const float muP = 1.f / (float)BB + 1e-8f;
    __shared__ float Ts2[16 * 256];   // [warp*2+half][col]

    int t = threadIdx.x, lane = t & 31, warp = t >> 5;
    int half = lane >> 4, hl = lane & 15;
    const int nW = NBLK * 8;          // 3552 warps
    const int nB = BB / 2;            // 32768 batches of 2 rows
    int gw = blockIdx.x * 8 + warp;

    for (int it = 1; it <= NITER; it++) {
        int prev = (it - 1) % 3, cur = it % 3, clr = (it + 1) % 3;

        float w[16];
#pragma unroll
        for (int m = 0; m < 16; m++)
            w[m] = nuP * __fdividef(1.f, __ldcg(&g_T[prev][(hl * 16 + m) * 32]));

        float tj[16];
#pragma unroll
        for (int m = 0; m < 16; m++) tj[m] = 0.f;

        float A[16], Bf[16];
        iter_loadh(gw, half, hl, A);
        for (int b = gw; b < nB; b += 2 * nW) {
            int b1 = b + nW, b2 = b + 2 * nW;
            if (b1 < nB) iter_loadh(b1, half, hl, Bf);
            iter_compute(b, half, hl, A, w, tj, muP);
            if (b2 < nB) iter_loadh(b2, half, hl, A);
            if (b1 < nB) iter_compute(b1, half, hl, Bf, w, tj, muP);
        }

        // clear the buffer used as 'cur' two iterations from now
        if (blockIdx.x == 0) g_T[clr][t * 32] = 0.f;

        // block-local column reduction, then one global atomic per column
#pragma unroll
        for (int m = 0; m < 16; m++)
            Ts2[(warp * 2 + half) * 256 + hl * 16 + m] = tj[m];
        __syncthreads();
        {
            float s = 0.f;
#pragma unroll
            for (int r = 0; r < 16; r++) s += Ts2[r * 256 + t];
            atomicAdd(&g_T[cur][t * 32], s);
        }
        __syncthreads();

        // grid barrier: release-arrive, acquire-spin (monotonic counter)
        if (t == 0) {
            asm volatile("red.release.gpu.global.add.u32 [%0], 1;"
                         :: "l"(&g_bar) : "memory");
            unsigned target = (unsigned)it * NBLK;
            unsigned v;
            do {
                asm volatile("ld.global.acquire.gpu.u32 %0, [%1];"
                             : "=r"(v) : "l"(&g_bar));
            } while (v < target);
        }
        __syncthreads();
    }
}

// ---------------------------------------------------------------------------
// final: sum_ij a_i * K'_ij * w_j * C_ij * softmax(|coord_i|)_j
// C reconstructed: C = -0.1 * log(K' - 1e-8). Persistent grid 444.
// ---------------------------------------------------------------------------
__global__ void __launch_bounds__(256, 3) k_final(const float* __restrict__ coord, int cur) {
    const float nuP = 1.f / (float)KK + 1e-8f;
    int t = threadIdx.x, lane = t & 31, warp = t >> 5;

    float w[8];
#pragma unroll
    for (int m = 0; m < 8; m++)
        w[m] = nuP * __fdividef(1.f, g_T[cur][(lane * 8 + m) * 32]);

    float accf = 0.f;
    const int nWarps = NBLK * 8;
    const int nBatch = BB / 2;   // batches of 2 rows
    int gw = blockIdx.x * 8 + warp;
    int colOff = lane * 8;

    for (int b = gw; b < nBatch; b += nWarps) {
        int row0 = b * 2;
#pragma unroll
        for (int r = 0; r < 2; r++) {
            int row = row0 + r;
            float q[8];
            {
                const float4* Cd = (const float4*)(coord + (size_t)row * KK + colOff);
                float4 c0 = Cd[0], c1 = Cd[1];
                q[0] = fabsf(c0.x); q[1] = fabsf(c0.y); q[2] = fabsf(c0.z); q[3] = fabsf(c0.w);
                q[4] = fabsf(c1.x); q[5] = fabsf(c1.y); q[6] = fabsf(c1.z); q[7] = fabsf(c1.w);
            }
            float mx = q[0];
#pragma unroll
            for (int m = 1; m < 8; m++) mx = fmaxf(mx, q[m]);
#pragma unroll
            for (int o = 16; o; o >>= 1) mx = fmaxf(mx, __shfl_xor_sync(0xffffffffu, mx, o));
            float e[8], z = 0.f;
#pragma unroll
            for (int m = 0; m < 8; m++) { e[m] = __expf(q[m] - mx); z += e[m]; }
#pragma unroll
            for (int o = 16; o; o >>= 1) z += __shfl_xor_sync(0xffffffffu, z, o);
            float rz = __fdividef(1.f, z);

            float a = g_a[row];
            float kk[8];
            {
                uint4 kv = *(const uint4*)&g_Kh[(size_t)row * KK + colOff];
                unsigned u[4] = {kv.x, kv.y, kv.z, kv.w};
#pragma unroll
                for (int i = 0; i < 4; i++) {
                    float2 f2 = __bfloat1622float2(*(__nv_bfloat162*)&u[i]);
                    kk[i * 2] = f2.x; kk[i * 2 + 1] = f2.y;
                }
            }

            float contrib = 0.f;
#pragma unroll
            for (int m = 0; m < 8; m++) {
                float cm = -0.1f * __logf(kk[m] - 1e-8f);   // reconstruct C
                contrib += kk[m] * w[m] * cm * e[m];
            }
            accf += a * rz * contrib;
        }
    }

#pragma unroll
    for (int o = 16; o; o >>= 1) accf += __shfl_xor_sync(0xffffffffu, accf, o);
    __shared__ double sw[8];
    if (lane == 0) sw[warp] = (double)accf;
    __syncthreads();
    if (t == 0) {
        double s = 0.0;
#pragma unroll
        for (int i = 0; i < 8; i++) s += sw[i];
        atomicAdd(&g_sum, s);
    }
}

__global__ void k_write(float* out) { out[0] = (float)g_sum; }

// ---------------------------------------------------------------------------
extern "C" void kernel_launch(void* const* d_in, const int* in_sizes, int n_in,
                              void* d_out, int out_size) {
    const float* x     = (const float*)d_in[0];   // (65536, 128)
    const float* proto = (const float*)d_in[1];   // (256, 128)
    const float* coord = (const float*)d_in[2];   // (65536, 256)

    k_init<<<1, 256>>>(proto);
    k_xnorm<<<BB / 8, 256>>>(x);
    k_gemm<<<BB / 64, 256>>>(x);

    k_sink<<<NBLK, 256>>>();

    k_final<<<NBLK, 256>>>(coord, NITER % 3);
    k_write<<<1, 1>>>((float*)d_out);
}

// round 8
// speedup vs baseline: 1.2196x; 1.2196x over previous
#include <cuda_runtime.h>
#include <cuda_bf16.h>
#include <math.h>

#define BB 65536
#define KK 256
#define DD 128
#define NBLK 296
#define NITER 50

typedef unsigned long long u64;

// ---- scratch (static device globals; no allocation) ----
__device__ __nv_bfloat16 g_Kh[(size_t)BB * KK];  // K' in bf16 (32MB) — L2-resident
__device__ float g_ynT[DD * KK];         // normalized prototypes, k-major [k][j]
__device__ float g_xinv[BB];             // 1 / ||x_i||
__device__ float g_a[BB];                // exp(u)  (written only on last iteration)
__device__ float g_T[3][KK * 32];        // column sums, padded 128B apart
__device__ unsigned g_bar;               // grid barrier counter
__device__ double g_sum;

// ---- packed f32x2 helpers ----
__device__ __forceinline__ void fma2(u64& d, u64 a, u64 b) {
    asm("fma.rn.f32x2 %0, %1, %2, %0;" : "+l"(d) : "l"(a), "l"(b));
}
__device__ __forceinline__ u64 add2(u64 a, u64 b) {
    u64 r; asm("add.rn.f32x2 %0, %1, %2;" : "=l"(r) : "l"(a), "l"(b)); return r;
}
__device__ __forceinline__ u64 packff(float lo, float hi) {
    u64 r;
    asm("mov.b64 %0, {%1, %2};" : "=l"(r) : "f"(lo), "f"(hi));
    return r;
}
__device__ __forceinline__ void unpackff(u64 v, float& lo, float& hi) {
    asm("mov.b64 {%0, %1}, %2;" : "=f"(lo), "=f"(hi) : "l"(v));
}
// two bf16 in a u32 -> packed f32x2 (bf16->f32 = 16-bit shift)
__device__ __forceinline__ u64 bf2_to_f32x2(unsigned v) {
    unsigned lo = v << 16;
    unsigned hi = v & 0xFFFF0000u;
    u64 r;
    asm("mov.b64 %0, {%1, %2};" : "=l"(r) : "r"(lo), "r"(hi));
    return r;
}

// ---------------------------------------------------------------------------
__global__ void k_init(const float* __restrict__ proto) {
    int j = threadIdx.x;  // 0..255
    float ss = 0.f;
#pragma unroll 8
    for (int k = 0; k < DD; k++) { float v = proto[j * DD + k]; ss += v * v; }
    float inv = __fdividef(1.f, fmaxf(sqrtf(ss), 1e-12f));
    for (int k = 0; k < DD; k++) g_ynT[k * KK + j] = proto[j * DD + k] * inv;
    const float nuP = 1.f / (float)KK + 1e-8f;
    g_T[0][j * 32] = nuP;   // makes w == 1 on iteration 1 (v0 = 0)
    g_T[1][j * 32] = 0.f;   // accumulation target of iteration 1
    if (j == 0) { g_sum = 0.0; g_bar = 0u; }
}

// ---------------------------------------------------------------------------
__global__ void k_xnorm(const float* __restrict__ x) {
    int warp = threadIdx.x >> 5, lane = threadIdx.x & 31;
    int row = blockIdx.x * 8 + warp;
    float4 v = ((const float4*)(x + (size_t)row * DD))[lane];
    float ss = v.x * v.x + v.y * v.y + v.z * v.z + v.w * v.w;
#pragma unroll
    for (int o = 16; o; o >>= 1) ss += __shfl_xor_sync(0xffffffffu, ss, o);
    if (lane == 0) g_xinv[row] = __fdividef(1.f, fmaxf(sqrtf(ss), 1e-12f));
}

// ---------------------------------------------------------------------------
// cost GEMM: K' = exp(-10*(1 - xn.yn)) + 1e-8, stored bf16
// ---------------------------------------------------------------------------
__global__ void k_gemm(const float* __restrict__ x) {
    __shared__ float ys[32 * 256];  // k-chunk of prototypes [kk][col]  (32KB)
    __shared__ float xs[64 * 32];   // x tile [row][kk]                 (8KB)
    __shared__ float xrn[64];

    int t = threadIdx.x;
    int rowBase = blockIdx.x * 64;
    if (t < 64) xrn[t] = g_xinv[rowBase + t];

    int tx = t & 31, ty = t >> 5;
    float acc[8][8];
#pragma unroll
    for (int i = 0; i < 8; i++)
#pragma unroll
        for (int j = 0; j < 8; j++) acc[i][j] = 0.f;

    for (int kc = 0; kc < 4; kc++) {
        __syncthreads();
        {
            const float4* src = (const float4*)(g_ynT + kc * 32 * 256);
            float4* dst = (float4*)ys;
#pragma unroll
            for (int i = 0; i < 8; i++) dst[t + i * 256] = src[t + i * 256];
        }
        {
#pragma unroll
            for (int i = 0; i < 2; i++) {
                int idx = t + i * 256;
                int r = idx >> 3;
                int c4 = idx & 7;
                float4 v = *(const float4*)(x + (size_t)(rowBase + r) * DD + kc * 32 + c4 * 4);
                *(float4*)&xs[r * 32 + c4 * 4] = v;
            }
        }
        __syncthreads();
#pragma unroll 4
        for (int k = 0; k < 32; k++) {
            float4 b0 = *(const float4*)&ys[k * 256 + tx * 8];
            float4 b1 = *(const float4*)&ys[k * 256 + tx * 8 + 4];
#pragma unroll
            for (int i = 0; i < 8; i++) {
                float a = xs[(ty * 8 + i) * 32 + k];
                acc[i][0] += a * b0.x; acc[i][1] += a * b0.y;
                acc[i][2] += a * b0.z; acc[i][3] += a * b0.w;
                acc[i][4] += a * b1.x; acc[i][5] += a * b1.y;
                acc[i][6] += a * b1.z; acc[i][7] += a * b1.w;
            }
        }
    }

#pragma unroll
    for (int i = 0; i < 8; i++) {
        int row = rowBase + ty * 8 + i;
        float inv = xrn[ty * 8 + i];
        float kv[8];
#pragma unroll
        for (int j = 0; j < 8; j++) {
            float c = 1.f - acc[i][j] * inv;
            kv[j] = __expf(-10.f * c) + 1e-8f;
        }
        __nv_bfloat162 h0 = __float22bfloat162_rn(make_float2(kv[0], kv[1]));
        __nv_bfloat162 h1 = __float22bfloat162_rn(make_float2(kv[2], kv[3]));
        __nv_bfloat162 h2 = __float22bfloat162_rn(make_float2(kv[4], kv[5]));
        __nv_bfloat162 h3 = __float22bfloat162_rn(make_float2(kv[6], kv[7]));
        uint4 s;
        s.x = *(unsigned*)&h0; s.y = *(unsigned*)&h1;
        s.z = *(unsigned*)&h2; s.w = *(unsigned*)&h3;
        *(uint4*)&g_Kh[(size_t)row * KK + tx * 8] = s;
    }
}

// ---------------------------------------------------------------------------
// k_sink helpers: batch = 2 rows; lanes 0-15 -> row 2b, lanes 16-31 -> row 2b+1
// each lane loads 16 bf16 (32B) kept PACKED in 4 u64 regs.
// ---------------------------------------------------------------------------
__device__ __forceinline__ void ldq(int b, int half, int hl, u64* q) {
    const __nv_bfloat16* p = g_Kh + ((size_t)b * 2 + half) * KK + hl * 16;
    asm volatile("ld.global.L2::evict_last.v4.b64 {%0,%1,%2,%3}, [%4];"
                 : "=l"(q[0]), "=l"(q[1]), "=l"(q[2]), "=l"(q[3]) : "l"(p));
}

__device__ __forceinline__ void computeq(int b, int half, int hl, const u64* q,
                                         const u64* w2, u64* tj2, float muP,
                                         bool storeA) {
    // unpack 16 bf16 -> 8 packed f32x2 pairs
    u64 pr[8];
#pragma unroll
    for (int i = 0; i < 4; i++) {
        unsigned lo32 = (unsigned)(q[i] & 0xffffffffull);
        unsigned hi32 = (unsigned)(q[i] >> 32);
        pr[2 * i]     = bf2_to_f32x2(lo32);
        pr[2 * i + 1] = bf2_to_f32x2(hi32);
    }
    // s = sum pr*w  (4 independent packed chains, then tree)
    u64 t0 = 0, t1 = 0, t2 = 0, t3 = 0;
    fma2(t0, pr[0], w2[0]); fma2(t1, pr[1], w2[1]);
    fma2(t2, pr[2], w2[2]); fma2(t3, pr[3], w2[3]);
    fma2(t0, pr[4], w2[4]); fma2(t1, pr[5], w2[5]);
    fma2(t2, pr[6], w2[6]); fma2(t3, pr[7], w2[7]);
    u64 tt = add2(add2(t0, t1), add2(t2, t3));
    float slo, shi; unpackff(tt, slo, shi);
    float s = slo + shi;
#pragma unroll
    for (int o = 8; o; o >>= 1) s += __shfl_xor_sync(0xffffffffu, s, o);
    float a = muP * __fdividef(1.f, s);
    if (storeA && hl == 0) g_a[b * 2 + half] = a;
    u64 a2 = packff(a, a);
#pragma unroll
    for (int k = 0; k < 8; k++) fma2(tj2[k], pr[k], a2);
}

// ---------------------------------------------------------------------------
// ALL 50 Sinkhorn iterations, persistent grid 296 (148 SMs x 2 blocks),
// device grid barrier; 3-deep packed load pipeline, f32x2 math.
// ---------------------------------------------------------------------------
__global__ void __launch_bounds__(256, 2) k_sink() {
    const float nuP = 1.f / (float)KK + 1e-8f;
    const float muP = 1.f / (float)BB + 1e-8f;
    __shared__ float Ts2[16 * 256];   // [warp*2+half][col]

    int t = threadIdx.x, lane = t & 31, warp = t >> 5;
    int half = lane >> 4, hl = lane & 15;
    const int nW = NBLK * 8;          // 2368 warps
    const int nB = BB / 2;            // 32768 batches of 2 rows
    int gw = blockIdx.x * 8 + warp;

    for (int it = 1; it <= NITER; it++) {
        int prev = (it - 1) % 3, cur = it % 3, clr = (it + 1) % 3;
        bool last = (it == NITER);

        u64 w2[8];
#pragma unroll
        for (int m = 0; m < 8; m++) {
            float wl = nuP * __fdividef(1.f, __ldcg(&g_T[prev][(hl * 16 + 2 * m) * 32]));
            float wh = nuP * __fdividef(1.f, __ldcg(&g_T[prev][(hl * 16 + 2 * m + 1) * 32]));
            w2[m] = packff(wl, wh);
        }

        u64 tj2[8];
#pragma unroll
        for (int m = 0; m < 8; m++) tj2[m] = 0ull;

        // 3-buffer pipeline: 2 loads in flight during every compute
        u64 qa[4], qb[4], qc[4];
        ldq(gw, half, hl, qa);
        if (gw + nW < nB) ldq(gw + nW, half, hl, qb);
        for (int b = gw; b < nB; b += 3 * nW) {
            int b1 = b + nW, b2 = b + 2 * nW, b3 = b + 3 * nW, b4 = b + 4 * nW;
            if (b2 < nB) ldq(b2, half, hl, qc);
            computeq(b, half, hl, qa, w2, tj2, muP, last);
            if (b3 < nB) ldq(b3, half, hl, qa);
            if (b1 < nB) computeq(b1, half, hl, qb, w2, tj2, muP, last);
            if (b4 < nB) ldq(b4, half, hl, qb);
            if (b2 < nB) computeq(b2, half, hl, qc, w2, tj2, muP, last);
        }

        // clear the buffer used as 'cur' two iterations from now
        if (blockIdx.x == 0) g_T[clr][t * 32] = 0.f;

        // block-local column reduction, then one global atomic per column
#pragma unroll
        for (int m = 0; m < 8; m++) {
            float lo, hi; unpackff(tj2[m], lo, hi);
            Ts2[(warp * 2 + half) * 256 + hl * 16 + 2 * m] = lo;
            Ts2[(warp * 2 + half) * 256 + hl * 16 + 2 * m + 1] = hi;
        }
        __syncthreads();
        {
            float s = 0.f;
#pragma unroll
            for (int r = 0; r < 16; r++) s += Ts2[r * 256 + t];
            atomicAdd(&g_T[cur][t * 32], s);
        }
        __syncthreads();

        // grid barrier: release-arrive, acquire-spin (monotonic counter)
        if (t == 0) {
            asm volatile("red.release.gpu.global.add.u32 [%0], 1;"
                         :: "l"(&g_bar) : "memory");
            unsigned target = (unsigned)it * NBLK;
            unsigned v;
            while (true) {
                asm volatile("ld.global.acquire.gpu.u32 %0, [%1];"
                             : "=r"(v) : "l"(&g_bar));
                if (v >= target) break;
                __nanosleep(32);
            }
        }
        __syncthreads();
    }
}

// ---------------------------------------------------------------------------
// final: sum_ij a_i * K'_ij * w_j * C_ij * softmax(|coord_i|)_j
// C reconstructed: C = -0.1 * log(K' - 1e-8). Persistent grid NBLK.
// ---------------------------------------------------------------------------
__global__ void __launch_bounds__(256, 2) k_final(const float* __restrict__ coord, int cur) {
    const float nuP = 1.f / (float)KK + 1e-8f;
    int t = threadIdx.x, lane = t & 31, warp = t >> 5;

    float w[8];
#pragma unroll
    for (int m = 0; m < 8; m++)
        w[m] = nuP * __fdividef(1.f, g_T[cur][(lane * 8 + m) * 32]);

    float accf = 0.f;
    const int nWarps = NBLK * 8;
    const int nBatch = BB / 2;   // batches of 2 rows
    int gw = blockIdx.x * 8 + warp;
    int colOff = lane * 8;

    for (int b = gw; b < nBatch; b += nWarps) {
        int row0 = b * 2;
#pragma unroll
        for (int r = 0; r < 2; r++) {
            int row = row0 + r;
            float q[8];
            {
                const float4* Cd = (const float4*)(coord + (size_t)row * KK + colOff);
                float4 c0 = Cd[0], c1 = Cd[1];
                q[0] = fabsf(c0.x); q[1] = fabsf(c0.y); q[2] = fabsf(c0.z); q[3] = fabsf(c0.w);
                q[4] = fabsf(c1.x); q[5] = fabsf(c1.y); q[6] = fabsf(c1.z); q[7] = fabsf(c1.w);
            }
            float mx = q[0];
#pragma unroll
            for (int m = 1; m < 8; m++) mx = fmaxf(mx, q[m]);
#pragma unroll
            for (int o = 16; o; o >>= 1) mx = fmaxf(mx, __shfl_xor_sync(0xffffffffu, mx, o));
            float e[8], z = 0.f;
#pragma unroll
            for (int m = 0; m < 8; m++) { e[m] = __expf(q[m] - mx); z += e[m]; }
#pragma unroll
            for (int o = 16; o; o >>= 1) z += __shfl_xor_sync(0xffffffffu, z, o);
            float rz = __fdividef(1.f, z);

            float a = g_a[row];
            float kk[8];
            {
                uint4 kv = *(const uint4*)&g_Kh[(size_t)row * KK + colOff];
                unsigned u[4] = {kv.x, kv.y, kv.z, kv.w};
#pragma unroll
                for (int i = 0; i < 4; i++) {
                    float2 f2 = __bfloat1622float2(*(__nv_bfloat162*)&u[i]);
                    kk[i * 2] = f2.x; kk[i * 2 + 1] = f2.y;
                }
            }

            float contrib = 0.f;
#pragma unroll
            for (int m = 0; m < 8; m++) {
                float cm = -0.1f * __logf(kk[m] - 1e-8f);   // reconstruct C
                contrib += kk[m] * w[m] * cm * e[m];
            }
            accf += a * rz * contrib;
        }
    }

#pragma unroll
    for (int o = 16; o; o >>= 1) accf += __shfl_xor_sync(0xffffffffu, accf, o);
    __shared__ double sw[8];
    if (lane == 0) sw[warp] = (double)accf;
    __syncthreads();
    if (t == 0) {
        double s = 0.0;
#pragma unroll
        for (int i = 0; i < 8; i++) s += sw[i];
        atomicAdd(&g_sum, s);
    }
}

__global__ void k_write(float* out) { out[0] = (float)g_sum; }

// ---------------------------------------------------------------------------
extern "C" void kernel_launch(void* const* d_in, const int* in_sizes, int n_in,
                              void* d_out, int out_size) {
    const float* x     = (const float*)d_in[0];   // (65536, 128)
    const float* proto = (const float*)d_in[1];   // (256, 128)
    const float* coord = (const float*)d_in[2];   // (65536, 256)

    k_init<<<1, 256>>>(proto);
    k_xnorm<<<BB / 8, 256>>>(x);
    k_gemm<<<BB / 64, 256>>>(x);

    k_sink<<<NBLK, 256>>>();

    k_final<<<NBLK, 256>>>(coord, NITER % 3);
    k_write<<<1, 1>>>((float*)d_out);
}

// round 9
// speedup vs baseline: 1.2656x; 1.0377x over previous
#include <cuda_runtime.h>
#include <cuda_bf16.h>
#include <cuda_fp16.h>
#include <cuda_fp8.h>
#include <math.h>

#define BB 65536
#define KK 256
#define DD 128
#define NBLK 296
#define NITER 50
#define KSCALE 8192.0f

typedef unsigned long long u64;

// ---- scratch (static device globals; no allocation) ----
__device__ unsigned char g_K8[(size_t)BB * KK];   // K'' = 2^13 * K' in e4m3 (16MB) — L1/L2-resident
__device__ __nv_bfloat16 g_Ch[(size_t)BB * KK];   // C in bf16 (32MB) — read once by k_final
__device__ float g_ynT[DD * KK];         // normalized prototypes, k-major [k][j]
__device__ float g_xinv[BB];             // 1 / ||x_i||
__device__ float g_a[BB];                // a'' = a / 2^13 (written only on last iteration)
__device__ float g_T[3][KK * 32];        // column sums (scale-invariant), padded 128B apart
__device__ unsigned g_bar;               // grid barrier counter
__device__ double g_sum;

// 4 packed e4m3 (one u32) -> 2 half2 (exact conversion; e4m3 ⊂ fp16)
__device__ __forceinline__ void fp8x4_to_h2x2(unsigned v, __half2& h0, __half2& h1) {
    unsigned r0, r1;
    asm("{.reg .b16 l,h;\n\t"
        "mov.b32 {l,h}, %2;\n\t"
        "cvt.rn.f16x2.e4m3x2 %0, l;\n\t"
        "cvt.rn.f16x2.e4m3x2 %1, h;}\n"
        : "=r"(r0), "=r"(r1) : "r"(v));
    h0 = *(__half2*)&r0; h1 = *(__half2*)&r1;
}

// ---------------------------------------------------------------------------
__global__ void k_init(const float* __restrict__ proto) {
    int j = threadIdx.x;  // 0..255
    float ss = 0.f;
#pragma unroll 8
    for (int k = 0; k < DD; k++) { float v = proto[j * DD + k]; ss += v * v; }
    float inv = __fdividef(1.f, fmaxf(sqrtf(ss), 1e-12f));
    for (int k = 0; k < DD; k++) g_ynT[k * KK + j] = proto[j * DD + k] * inv;
    const float nuP = 1.f / (float)KK + 1e-8f;
    g_T[0][j * 32] = nuP;   // makes w == 1 on iteration 1 (v0 = 0)
    g_T[1][j * 32] = 0.f;   // accumulation target of iteration 1
    if (j == 0) { g_sum = 0.0; g_bar = 0u; }
}

// ---------------------------------------------------------------------------
__global__ void k_xnorm(const float* __restrict__ x) {
    int warp = threadIdx.x >> 5, lane = threadIdx.x & 31;
    int row = blockIdx.x * 8 + warp;
    float4 v = ((const float4*)(x + (size_t)row * DD))[lane];
    float ss = v.x * v.x + v.y * v.y + v.z * v.z + v.w * v.w;
#pragma unroll
    for (int o = 16; o; o >>= 1) ss += __shfl_xor_sync(0xffffffffu, ss, o);
    if (lane == 0) g_xinv[row] = __fdividef(1.f, fmaxf(sqrtf(ss), 1e-12f));
}

// ---------------------------------------------------------------------------
// cost GEMM: C = 1 - xn.yn (bf16), K'' = 2^13*(exp(-10C)+1e-8) (e4m3)
// ---------------------------------------------------------------------------
__global__ void k_gemm(const float* __restrict__ x) {
    __shared__ float ys[32 * 256];  // k-chunk of prototypes [kk][col]  (32KB)
    __shared__ float xs[64 * 32];   // x tile [row][kk]                 (8KB)
    __shared__ float xrn[64];

    int t = threadIdx.x;
    int rowBase = blockIdx.x * 64;
    if (t < 64) xrn[t] = g_xinv[rowBase + t];

    int tx = t & 31, ty = t >> 5;
    float acc[8][8];
#pragma unroll
    for (int i = 0; i < 8; i++)
#pragma unroll
        for (int j = 0; j < 8; j++) acc[i][j] = 0.f;

    for (int kc = 0; kc < 4; kc++) {
        __syncthreads();
        {
            const float4* src = (const float4*)(g_ynT + kc * 32 * 256);
            float4* dst = (float4*)ys;
#pragma unroll
            for (int i = 0; i < 8; i++) dst[t + i * 256] = src[t + i * 256];
        }
        {
#pragma unroll
            for (int i = 0; i < 2; i++) {
                int idx = t + i * 256;
                int r = idx >> 3;
                int c4 = idx & 7;
                float4 v = *(const float4*)(x + (size_t)(rowBase + r) * DD + kc * 32 + c4 * 4);
                *(float4*)&xs[r * 32 + c4 * 4] = v;
            }
        }
        __syncthreads();
#pragma unroll 4
        for (int k = 0; k < 32; k++) {
            float4 b0 = *(const float4*)&ys[k * 256 + tx * 8];
            float4 b1 = *(const float4*)&ys[k * 256 + tx * 8 + 4];
#pragma unroll
            for (int i = 0; i < 8; i++) {
                float a = xs[(ty * 8 + i) * 32 + k];
                acc[i][0] += a * b0.x; acc[i][1] += a * b0.y;
                acc[i][2] += a * b0.z; acc[i][3] += a * b0.w;
                acc[i][4] += a * b1.x; acc[i][5] += a * b1.y;
                acc[i][6] += a * b1.z; acc[i][7] += a * b1.w;
            }
        }
    }

#pragma unroll
    for (int i = 0; i < 8; i++) {
        int row = rowBase + ty * 8 + i;
        float inv = xrn[ty * 8 + i];
        float c[8], kv[8];
#pragma unroll
        for (int j = 0; j < 8; j++) {
            c[j] = 1.f - acc[i][j] * inv;
            kv[j] = (__expf(-10.f * c[j]) + 1e-8f) * KSCALE;
        }
        // C in bf16
        __nv_bfloat162 h0 = __float22bfloat162_rn(make_float2(c[0], c[1]));
        __nv_bfloat162 h1 = __float22bfloat162_rn(make_float2(c[2], c[3]));
        __nv_bfloat162 h2 = __float22bfloat162_rn(make_float2(c[4], c[5]));
        __nv_bfloat162 h3 = __float22bfloat162_rn(make_float2(c[6], c[7]));
        uint4 sc;
        sc.x = *(unsigned*)&h0; sc.y = *(unsigned*)&h1;
        sc.z = *(unsigned*)&h2; sc.w = *(unsigned*)&h3;
        *(uint4*)&g_Ch[(size_t)row * KK + tx * 8] = sc;
        // K'' in e4m3 (satfinite)
        __nv_fp8x2_storage_t p0 = __nv_cvt_float2_to_fp8x2(make_float2(kv[0], kv[1]), __NV_SATFINITE, __NV_E4M3);
        __nv_fp8x2_storage_t p1 = __nv_cvt_float2_to_fp8x2(make_float2(kv[2], kv[3]), __NV_SATFINITE, __NV_E4M3);
        __nv_fp8x2_storage_t p2 = __nv_cvt_float2_to_fp8x2(make_float2(kv[4], kv[5]), __NV_SATFINITE, __NV_E4M3);
        __nv_fp8x2_storage_t p3 = __nv_cvt_float2_to_fp8x2(make_float2(kv[6], kv[7]), __NV_SATFINITE, __NV_E4M3);
        u64 pk = (u64)p0 | ((u64)p1 << 16) | ((u64)p2 << 32) | ((u64)p3 << 48);
        *(u64*)&g_K8[(size_t)row * KK + tx * 8] = pk;
    }
}

// ---------------------------------------------------------------------------
// k_sink helpers: batch = 4 rows; lane group g=lane>>3 owns row 4b+g,
// gl=lane&7 owns cols [gl*32, gl*32+32). One LDG.256 (32 fp8) per lane/batch.
// ---------------------------------------------------------------------------
__device__ __forceinline__ void ldq8(const unsigned char* p, u64* q) {
    asm volatile("ld.global.L2::evict_last.v4.b64 {%0,%1,%2,%3}, [%4];"
                 : "=l"(q[0]), "=l"(q[1]), "=l"(q[2]), "=l"(q[3]) : "l"(p));
}

__device__ __forceinline__ void comp8(int row, const u64* q, const __half2* wh,
                                      __half2* tj, float muP, bool storeA, int gl) {
    __half2 kh[16];
#pragma unroll
    for (int i = 0; i < 4; i++) {
        fp8x4_to_h2x2((unsigned)(q[i] & 0xffffffffull), kh[4 * i], kh[4 * i + 1]);
        fp8x4_to_h2x2((unsigned)(q[i] >> 32), kh[4 * i + 2], kh[4 * i + 3]);
    }
    __half2 s0 = __float2half2_rn(0.f), s1 = s0, s2 = s0, s3 = s0;
#pragma unroll
    for (int i = 0; i < 16; i += 4) {
        s0 = __hfma2(kh[i], wh[i], s0);
        s1 = __hfma2(kh[i + 1], wh[i + 1], s1);
        s2 = __hfma2(kh[i + 2], wh[i + 2], s2);
        s3 = __hfma2(kh[i + 3], wh[i + 3], s3);
    }
    s0 = __hadd2(__hadd2(s0, s1), __hadd2(s2, s3));
    float s = __low2float(s0) + __high2float(s0);
#pragma unroll
    for (int o = 4; o; o >>= 1) s += __shfl_xor_sync(0xffffffffu, s, o);
    float a = muP * __fdividef(1.f, s);
    if (storeA && gl == 0) g_a[row] = a;
    __half2 a2 = __float2half2_rn(a);
#pragma unroll
    for (int i = 0; i < 16; i++) tj[i] = __hfma2(kh[i], a2, tj[i]);
}

// ---------------------------------------------------------------------------
// ALL 50 Sinkhorn iterations, persistent grid 296 (148 SMs x 2 blocks),
// device grid barrier; fp8 K (L1-resident), fp16 packed math.
// ---------------------------------------------------------------------------
__global__ void __launch_bounds__(256, 2) k_sink() {
    const float nuP = 1.f / (float)KK + 1e-8f;
    const float muP = 1.f / (float)BB + 1e-8f;
    __shared__ float2 Ts2[32 * 128];   // 32 KB: [warp*4+g][128 col-pairs]
    __shared__ float wsh[256];

    int t = threadIdx.x, lane = t & 31, warp = t >> 5;
    int g = lane >> 3, gl = lane & 7;
    const int nW = NBLK * 8;           // 2368 warps
    const int nB = BB / 4;             // 16384 batches of 4 rows
    int gw = blockIdx.x * 8 + warp;
    const unsigned char* base = g_K8 + (size_t)gl * 32;

    for (int it = 1; it <= NITER; it++) {
        int prev = (it - 1) % 3, cur = it % 3, clr = (it + 1) % 3;
        bool last = (it == NITER);

        // w computed once per block (1 div/thread), broadcast via smem
        wsh[t] = nuP * __fdividef(1.f, __ldcg(&g_T[prev][t * 32]));
        __syncthreads();

        __half2 wh[16];
        const float2* wp = (const float2*)&wsh[gl * 32];
#pragma unroll
        for (int i = 0; i < 16; i++) wh[i] = __float22half2_rn(wp[i]);

        __half2 tj[16];
        __half2 z2 = __float2half2_rn(0.f);
#pragma unroll
        for (int i = 0; i < 16; i++) tj[i] = z2;

        u64 qa[4], qb[4];
        ldq8(base + ((size_t)gw * 4 + g) * KK, qa);
        for (int b = gw; b < nB; b += 2 * nW) {
            int b1 = b + nW, b2 = b + 2 * nW;
            if (b1 < nB) ldq8(base + ((size_t)b1 * 4 + g) * KK, qb);
            comp8(b * 4 + g, qa, wh, tj, muP, last, gl);
            if (b2 < nB) ldq8(base + ((size_t)b2 * 4 + g) * KK, qa);
            if (b1 < nB) comp8(b1 * 4 + g, qb, wh, tj, muP, last, gl);
        }

        // clear the buffer that becomes 'cur' next iteration (idle this iter)
        if (blockIdx.x == 0) g_T[clr][t * 32] = 0.f;

        // block-local column reduction, then one global atomic per column
        float2* dst = &Ts2[(warp * 4 + g) * 128 + gl * 16];
#pragma unroll
        for (int i = 0; i < 16; i++) dst[i] = __half22float2(tj[i]);
        __syncthreads();
        {
            const float* T1 = (const float*)Ts2;
            float s0 = 0.f, s1 = 0.f, s2 = 0.f, s3 = 0.f;
#pragma unroll
            for (int r = 0; r < 32; r += 4) {
                s0 += T1[r * 256 + t];
                s1 += T1[(r + 1) * 256 + t];
                s2 += T1[(r + 2) * 256 + t];
                s3 += T1[(r + 3) * 256 + t];
            }
            atomicAdd(&g_T[cur][t * 32], (s0 + s1) + (s2 + s3));
        }
        __syncthreads();

        // grid barrier: release-arrive, acquire-spin (monotonic counter)
        if (t == 0) {
            asm volatile("red.release.gpu.global.add.u32 [%0], 1;"
                         :: "l"(&g_bar) : "memory");
            unsigned target = (unsigned)it * NBLK;
            unsigned v;
            while (true) {
                asm volatile("ld.global.acquire.gpu.u32 %0, [%1];"
                             : "=r"(v) : "l"(&g_bar));
                if (v >= target) break;
                __nanosleep(32);
            }
        }
        __syncthreads();
    }
}

// ---------------------------------------------------------------------------
// final: sum_ij a_i * K''_ij * w_j * C_ij * softmax(|coord_i|)_j
// (a stores a/2^13, K'' = 2^13 K' -> product exact). C read from bf16 store.
// ---------------------------------------------------------------------------
__global__ void __launch_bounds__(256, 2) k_final(const float* __restrict__ coord, int cur) {
    const float nuP = 1.f / (float)KK + 1e-8f;
    int t = threadIdx.x, lane = t & 31, warp = t >> 5;

    float w[8];
#pragma unroll
    for (int m = 0; m < 8; m++)
        w[m] = nuP * __fdividef(1.f, g_T[cur][(lane * 8 + m) * 32]);

    float accf = 0.f;
    const int nWarps = NBLK * 8;
    const int nBatch = BB / 2;   // batches of 2 rows
    int gw = blockIdx.x * 8 + warp;
    int colOff = lane * 8;

    for (int b = gw; b < nBatch; b += nWarps) {
        int row0 = b * 2;
#pragma unroll
        for (int r = 0; r < 2; r++) {
            int row = row0 + r;
            float q[8];
            {
                const float4* Cd = (const float4*)(coord + (size_t)row * KK + colOff);
                float4 c0 = Cd[0], c1 = Cd[1];
                q[0] = fabsf(c0.x); q[1] = fabsf(c0.y); q[2] = fabsf(c0.z); q[3] = fabsf(c0.w);
                q[4] = fabsf(c1.x); q[5] = fabsf(c1.y); q[6] = fabsf(c1.z); q[7] = fabsf(c1.w);
            }
            float mx = q[0];
#pragma unroll
            for (int m = 1; m < 8; m++) mx = fmaxf(mx, q[m]);
#pragma unroll
            for (int o = 16; o; o >>= 1) mx = fmaxf(mx, __shfl_xor_sync(0xffffffffu, mx, o));
            float e[8], z = 0.f;
#pragma unroll
            for (int m = 0; m < 8; m++) { e[m] = __expf(q[m] - mx); z += e[m]; }
#pragma unroll
            for (int o = 16; o; o >>= 1) z += __shfl_xor_sync(0xffffffffu, z, o);
            float rz = __fdividef(1.f, z);

            float a = g_a[row];

            // K'' fp8 -> f32
            float kk[8];
            {
                u64 kq = *(const u64*)&g_K8[(size_t)row * KK + colOff];
                __half2 h0, h1, h2, h3;
                fp8x4_to_h2x2((unsigned)(kq & 0xffffffffull), h0, h1);
                fp8x4_to_h2x2((unsigned)(kq >> 32), h2, h3);
                float2 f;
                f = __half22float2(h0); kk[0] = f.x; kk[1] = f.y;
                f = __half22float2(h1); kk[2] = f.x; kk[3] = f.y;
                f = __half22float2(h2); kk[4] = f.x; kk[5] = f.y;
                f = __half22float2(h3); kk[6] = f.x; kk[7] = f.y;
            }
            // C bf16 -> f32
            float cm[8];
            {
                uint4 cv = *(const uint4*)&g_Ch[(size_t)row * KK + colOff];
                unsigned u[4] = {cv.x, cv.y, cv.z, cv.w};
#pragma unroll
                for (int i = 0; i < 4; i++) {
                    float2 f2 = __bfloat1622float2(*(__nv_bfloat162*)&u[i]);
                    cm[i * 2] = f2.x; cm[i * 2 + 1] = f2.y;
                }
            }

            float contrib = 0.f;
#pragma unroll
            for (int m = 0; m < 8; m++)
                contrib += kk[m] * w[m] * cm[m] * e[m];
            accf += a * rz * contrib;
        }
    }

#pragma unroll
    for (int o = 16; o; o >>= 1) accf += __shfl_xor_sync(0xffffffffu, accf, o);
    __shared__ double sw[8];
    if (lane == 0) sw[warp] = (double)accf;
    __syncthreads();
    if (t == 0) {
        double s = 0.0;
#pragma unroll
        for (int i = 0; i < 8; i++) s += sw[i];
        atomicAdd(&g_sum, s);
    }
}

__global__ void k_write(float* out) { out[0] = (float)g_sum; }

// ---------------------------------------------------------------------------
extern "C" void kernel_launch(void* const* d_in, const int* in_sizes, int n_in,
                              void* d_out, int out_size) {
    const float* x     = (const float*)d_in[0];   // (65536, 128)
    const float* proto = (const float*)d_in[1];   // (256, 128)
    const float* coord = (const float*)d_in[2];   // (65536, 256)

    k_init<<<1, 256>>>(proto);
    k_xnorm<<<BB / 8, 256>>>(x);
    k_gemm<<<BB / 64, 256>>>(x);

    k_sink<<<NBLK, 256>>>();

    k_final<<<NBLK, 256>>>(coord, NITER % 3);
    k_write<<<1, 1>>>((float*)d_out);
}

// round 10
// speedup vs baseline: 1.3874x; 1.0962x over previous
#include <cuda_runtime.h>
#include <cuda_bf16.h>
#include <math.h>

#define BB 65536
#define KK 256
#define DD 128
#define NBLK 444
#define NITER 50

typedef unsigned long long u64;

// ---- scratch (static device globals; no allocation) ----
__device__ __nv_bfloat16 g_Kh[(size_t)BB * KK];  // K' in bf16 (32MB) — L2-resident
__device__ float g_ynT[DD * KK];         // normalized prototypes, k-major [k][j]
__device__ float g_xinv[BB];             // 1 / ||x_i||
__device__ float g_a[BB];                // exp(u)   (written on last iteration)
__device__ float g_T[3][KK * 32];        // column sums, padded 128B apart
__device__ unsigned g_bar;               // grid barrier counter
__device__ double g_sum;

// ---- packed f32x2 helpers ----
__device__ __forceinline__ void fma2(u64& d, u64 a, u64 b) {
    asm("fma.rn.f32x2 %0, %1, %2, %0;" : "+l"(d) : "l"(a), "l"(b));
}
__device__ __forceinline__ u64 add2(u64 a, u64 b) {
    u64 r; asm("add.rn.f32x2 %0, %1, %2;" : "=l"(r) : "l"(a), "l"(b)); return r;
}
__device__ __forceinline__ u64 packff(float lo, float hi) {
    u64 r; asm("mov.b64 %0, {%1, %2};" : "=l"(r) : "f"(lo), "f"(hi)); return r;
}
__device__ __forceinline__ void unpackff(u64 v, float& lo, float& hi) {
    asm("mov.b64 {%0, %1}, %2;" : "=f"(lo), "=f"(hi) : "l"(v));
}
// two bf16 in a u32 -> packed f32x2 (bf16->f32 = 16-bit shift)
__device__ __forceinline__ u64 bf2_to_f32x2(unsigned v) {
    unsigned lo = v << 16;
    unsigned hi = v & 0xFFFF0000u;
    u64 r; asm("mov.b64 %0, {%1, %2};" : "=l"(r) : "r"(lo), "r"(hi)); return r;
}

// ---------------------------------------------------------------------------
__global__ void k_init(const float* __restrict__ proto) {
    int j = threadIdx.x;  // 0..255
    float ss = 0.f;
#pragma unroll 8
    for (int k = 0; k < DD; k++) { float v = proto[j * DD + k]; ss += v * v; }
    float inv = __fdividef(1.f, fmaxf(sqrtf(ss), 1e-12f));
    for (int k = 0; k < DD; k++) g_ynT[k * KK + j] = proto[j * DD + k] * inv;
    const float nuP = 1.f / (float)KK + 1e-8f;
    g_T[0][j * 32] = nuP;   // makes w == 1 on iteration 1 (v0 = 0)
    g_T[1][j * 32] = 0.f;   // accumulation target of iteration 1
    if (j == 0) { g_sum = 0.0; g_bar = 0u; }
}

// ---------------------------------------------------------------------------
__global__ void k_xnorm(const float* __restrict__ x) {
    int warp = threadIdx.x >> 5, lane = threadIdx.x & 31;
    int row = blockIdx.x * 8 + warp;
    float4 v = ((const float4*)(x + (size_t)row * DD))[lane];
    float ss = v.x * v.x + v.y * v.y + v.z * v.z + v.w * v.w;
#pragma unroll
    for (int o = 16; o; o >>= 1) ss += __shfl_xor_sync(0xffffffffu, ss, o);
    if (lane == 0) g_xinv[row] = __fdividef(1.f, fmaxf(sqrtf(ss), 1e-12f));
}

// ---------------------------------------------------------------------------
// cost GEMM via packed FFMA2: K' = exp(-10*(1 - xn.yn)) + 1e-8, stored bf16
// block = 256 threads, 64 rows x 256 cols, 8x8 tile/thread (4 packed pairs/row)
// smem access pattern identical to the proven scalar version; only the FMA
// stream is packed (32 FFMA2 + 8 movs per k vs 64 FFMA).
// ---------------------------------------------------------------------------
__global__ void k_gemm(const float* __restrict__ x) {
    __shared__ float ys[32 * 256];  // k-chunk of prototypes [kk][col]  (32KB)
    __shared__ float xs[64 * 32];   // x tile [row][kk]                 (8KB)
    __shared__ float xrn[64];

    int t = threadIdx.x;
    int rowBase = blockIdx.x * 64;
    if (t < 64) xrn[t] = g_xinv[rowBase + t];

    int tx = t & 31, ty = t >> 5;
    u64 acc[8][4];
#pragma unroll
    for (int i = 0; i < 8; i++)
#pragma unroll
        for (int j = 0; j < 4; j++) acc[i][j] = 0ull;

    for (int kc = 0; kc < 4; kc++) {
        __syncthreads();
        {
            const float4* src = (const float4*)(g_ynT + kc * 32 * 256);
            float4* dst = (float4*)ys;
#pragma unroll
            for (int i = 0; i < 8; i++) dst[t + i * 256] = src[t + i * 256];
        }
        {
#pragma unroll
            for (int i = 0; i < 2; i++) {
                int idx = t + i * 256;
                int r = idx >> 3;
                int c4 = idx & 7;
                float4 v = *(const float4*)(x + (size_t)(rowBase + r) * DD + kc * 32 + c4 * 4);
                *(float4*)&xs[r * 32 + c4 * 4] = v;
            }
        }
        __syncthreads();
#pragma unroll 4
        for (int k = 0; k < 32; k++) {
            float4 b0 = *(const float4*)&ys[k * 256 + tx * 8];
            float4 b1 = *(const float4*)&ys[k * 256 + tx * 8 + 4];
            u64 p0 = packff(b0.x, b0.y), p1 = packff(b0.z, b0.w);
            u64 p2 = packff(b1.x, b1.y), p3 = packff(b1.z, b1.w);
#pragma unroll
            for (int i = 0; i < 8; i++) {
                float a = xs[(ty * 8 + i) * 32 + k];
                u64 a2 = packff(a, a);
                fma2(acc[i][0], a2, p0);
                fma2(acc[i][1], a2, p1);
                fma2(acc[i][2], a2, p2);
                fma2(acc[i][3], a2, p3);
            }
        }
    }

#pragma unroll
    for (int i = 0; i < 8; i++) {
        int row = rowBase + ty * 8 + i;
        float inv = xrn[ty * 8 + i];
        float kv[8];
#pragma unroll
        for (int j = 0; j < 4; j++) {
            float lo, hi; unpackff(acc[i][j], lo, hi);
            float c0 = 1.f - lo * inv;
            float c1 = 1.f - hi * inv;
            kv[2 * j]     = __expf(-10.f * c0) + 1e-8f;
            kv[2 * j + 1] = __expf(-10.f * c1) + 1e-8f;
        }
        __nv_bfloat162 h0 = __float22bfloat162_rn(make_float2(kv[0], kv[1]));
        __nv_bfloat162 h1 = __float22bfloat162_rn(make_float2(kv[2], kv[3]));
        __nv_bfloat162 h2 = __float22bfloat162_rn(make_float2(kv[4], kv[5]));
        __nv_bfloat162 h3 = __float22bfloat162_rn(make_float2(kv[6], kv[7]));
        uint4 s;
        s.x = *(unsigned*)&h0; s.y = *(unsigned*)&h1;
        s.z = *(unsigned*)&h2; s.w = *(unsigned*)&h3;
        *(uint4*)&g_Kh[(size_t)row * KK + tx * 8] = s;
    }
}

// ---------------------------------------------------------------------------
// k_sink helpers: batch = 2 rows; lanes 0-15 -> row 2b, lanes 16-31 -> row 2b+1
// each lane loads 16 bf16 (32B) kept PACKED in 4 u64 regs.
// ---------------------------------------------------------------------------
__device__ __forceinline__ void ldq(int b, int half, int hl, u64* q) {
    const __nv_bfloat16* p = g_Kh + ((size_t)b * 2 + half) * KK + hl * 16;
    asm volatile("ld.global.L2::evict_last.v4.b64 {%0,%1,%2,%3}, [%4];"
                 : "=l"(q[0]), "=l"(q[1]), "=l"(q[2]), "=l"(q[3]) : "l"(p));
}

__device__ __forceinline__ void computeq(int b, int half, int hl, const u64* q,
                                         const u64* w2, u64* tj2, float muP,
                                         bool storeA) {
    u64 pr[8];
#pragma unroll
    for (int i = 0; i < 4; i++) {
        unsigned lo32 = (unsigned)(q[i] & 0xffffffffull);
        unsigned hi32 = (unsigned)(q[i] >> 32);
        pr[2 * i]     = bf2_to_f32x2(lo32);
        pr[2 * i + 1] = bf2_to_f32x2(hi32);
    }
    u64 t0 = 0, t1 = 0, t2 = 0, t3 = 0;
    fma2(t0, pr[0], w2[0]); fma2(t1, pr[1], w2[1]);
    fma2(t2, pr[2], w2[2]); fma2(t3, pr[3], w2[3]);
    fma2(t0, pr[4], w2[4]); fma2(t1, pr[5], w2[5]);
    fma2(t2, pr[6], w2[6]); fma2(t3, pr[7], w2[7]);
    u64 tt = add2(add2(t0, t1), add2(t2, t3));
    float slo, shi; unpackff(tt, slo, shi);
    float s = slo + shi;
#pragma unroll
    for (int o = 8; o; o >>= 1) s += __shfl_xor_sync(0xffffffffu, s, o);
    float a = muP * __fdividef(1.f, s);
    if (storeA && hl == 0) g_a[b * 2 + half] = a;
    u64 a2 = packff(a, a);
#pragma unroll
    for (int k = 0; k < 8; k++) fma2(tj2[k], pr[k], a2);
}

// ---------------------------------------------------------------------------
// ALL 50 Sinkhorn iterations, persistent grid 444 (148 SMs x 3 blocks),
// device grid barrier; bf16 K, f32x2 math, 2-buffer pipeline.
// ---------------------------------------------------------------------------
__global__ void __launch_bounds__(256, 3) k_sink() {
    const float nuP = 1.f / (float)KK + 1e-8f;
    const float muP = 1.f / (float)BB + 1e-8f;
    __shared__ float Ts2[16 * 256];   // 16 KB: [warp*2+half][col]
    __shared__ float wsh[256];        // per-block w broadcast

    int t = threadIdx.x, lane = t & 31, warp = t >> 5;
    int half = lane >> 4, hl = lane & 15;
    const int nW = NBLK * 8;          // 3552 warps
    const int nB = BB / 2;            // 32768 batches of 2 rows
    int gw = blockIdx.x * 8 + warp;

    for (int it = 1; it <= NITER; it++) {
        int prev = (it - 1) % 3, cur = it % 3, clr = (it + 1) % 3;
        bool last = (it == NITER);

        // w once per block: 1 divide per thread, broadcast via smem
        wsh[t] = nuP * __fdividef(1.f, __ldcg(&g_T[prev][t * 32]));
        __syncthreads();

        u64 w2[8];
        const float2* wp = (const float2*)&wsh[hl * 16];
#pragma unroll
        for (int m = 0; m < 8; m++) w2[m] = packff(wp[m].x, wp[m].y);

        u64 tj2[8];
#pragma unroll
        for (int m = 0; m < 8; m++) tj2[m] = 0ull;

        // 2-buffer pipeline
        u64 qa[4], qb[4];
        ldq(gw, half, hl, qa);
        for (int b = gw; b < nB; b += 2 * nW) {
            int b1 = b + nW, b2 = b + 2 * nW;
            if (b1 < nB) ldq(b1, half, hl, qb);
            computeq(b, half, hl, qa, w2, tj2, muP, last);
            if (b2 < nB) ldq(b2, half, hl, qa);
            if (b1 < nB) computeq(b1, half, hl, qb, w2, tj2, muP, last);
        }

        // clear the buffer that becomes 'cur' next iteration (idle this iter)
        if (blockIdx.x == 0) g_T[clr][t * 32] = 0.f;

        // block-local column reduction, then one global atomic per column
#pragma unroll
        for (int m = 0; m < 8; m++) {
            float lo, hi; unpackff(tj2[m], lo, hi);
            Ts2[(warp * 2 + half) * 256 + hl * 16 + 2 * m] = lo;
            Ts2[(warp * 2 + half) * 256 + hl * 16 + 2 * m + 1] = hi;
        }
        __syncthreads();
        {
            float s = 0.f;
#pragma unroll
            for (int r = 0; r < 16; r++) s += Ts2[r * 256 + t];
            atomicAdd(&g_T[cur][t * 32], s);
        }
        __syncthreads();

        // grid barrier: release-arrive, acquire-spin (monotonic counter)
        if (t == 0) {
            asm volatile("red.release.gpu.global.add.u32 [%0], 1;"
                         :: "l"(&g_bar) : "memory");
            unsigned target = (unsigned)it * NBLK;
            unsigned v;
            while (true) {
                asm volatile("ld.global.acquire.gpu.u32 %0, [%1];"
                             : "=r"(v) : "l"(&g_bar));
                if (v >= target) break;
                __nanosleep(16);
            }
        }
        __syncthreads();
    }
}

// ---------------------------------------------------------------------------
// final: sum_ij a_i * K'_ij * w_j * C_ij * softmax(|coord_i|)_j
// C reconstructed: C = -0.1 * log(K' - 1e-8).
// ---------------------------------------------------------------------------
__global__ void __launch_bounds__(256, 2) k_final(const float* __restrict__ coord, int cur) {
    const float nuP = 1.f / (float)KK + 1e-8f;
    int t = threadIdx.x, lane = t & 31, warp = t >> 5;

    float w[8];
#pragma unroll
    for (int m = 0; m < 8; m++)
        w[m] = nuP * __fdividef(1.f, g_T[cur][(lane * 8 + m) * 32]);

    float accf = 0.f;
    const int nWarps = 296 * 8;
    const int nBatch = BB / 2;   // batches of 2 rows
    int gw = blockIdx.x * 8 + warp;
    int colOff = lane * 8;

    for (int b = gw; b < nBatch; b += nWarps) {
        int row0 = b * 2;
#pragma unroll
        for (int r = 0; r < 2; r++) {
            int row = row0 + r;
            float q[8];
            {
                const float4* Cd = (const float4*)(coord + (size_t)row * KK + colOff);
                float4 c0 = Cd[0], c1 = Cd[1];
                q[0] = fabsf(c0.x); q[1] = fabsf(c0.y); q[2] = fabsf(c0.z); q[3] = fabsf(c0.w);
                q[4] = fabsf(c1.x); q[5] = fabsf(c1.y); q[6] = fabsf(c1.z); q[7] = fabsf(c1.w);
            }
            float mx = q[0];
#pragma unroll
            for (int m = 1; m < 8; m++) mx = fmaxf(mx, q[m]);
#pragma unroll
            for (int o = 16; o; o >>= 1) mx = fmaxf(mx, __shfl_xor_sync(0xffffffffu, mx, o));
            float e[8], z = 0.f;
#pragma unroll
            for (int m = 0; m < 8; m++) { e[m] = __expf(q[m] - mx); z += e[m]; }
#pragma unroll
            for (int o = 16; o; o >>= 1) z += __shfl_xor_sync(0xffffffffu, z, o);
            float rz = __fdividef(1.f, z);

            float a = g_a[row];
            float kk[8];
            {
                uint4 kv = *(const uint4*)&g_Kh[(size_t)row * KK + colOff];
                unsigned u[4] = {kv.x, kv.y, kv.z, kv.w};
#pragma unroll
                for (int i = 0; i < 4; i++) {
                    float2 f2 = __bfloat1622float2(*(__nv_bfloat162*)&u[i]);
                    kk[i * 2] = f2.x; kk[i * 2 + 1] = f2.y;
                }
            }

            float contrib = 0.f;
#pragma unroll
            for (int m = 0; m < 8; m++) {
                float cm = -0.1f * __logf(kk[m] - 1e-8f);   // reconstruct C
                contrib += kk[m] * w[m] * cm * e[m];
            }
            accf += a * rz * contrib;
        }
    }

#pragma unroll
    for (int o = 16; o; o >>= 1) accf += __shfl_xor_sync(0xffffffffu, accf, o);
    __shared__ double sw[8];
    if (lane == 0) sw[warp] = (double)accf;
    __syncthreads();
    if (t == 0) {
        double s = 0.0;
#pragma unroll
        for (int i = 0; i < 8; i++) s += sw[i];
        atomicAdd(&g_sum, s);
    }
}

__global__ void k_write(float* out) { out[0] = (float)g_sum; }

// ---------------------------------------------------------------------------
extern "C" void kernel_launch(void* const* d_in, const int* in_sizes, int n_in,
                              void* d_out, int out_size) {
    const float* x     = (const float*)d_in[0];   // (65536, 128)
    const float* proto = (const float*)d_in[1];   // (256, 128)
    const float* coord = (const float*)d_in[2];   // (65536, 256)

    k_init<<<1, 256>>>(proto);
    k_xnorm<<<BB / 8, 256>>>(x);
    k_gemm<<<BB / 64, 256>>>(x);

    k_sink<<<NBLK, 256>>>();

    k_final<<<296, 256>>>(coord, NITER % 3);
    k_write<<<1, 1>>>((float*)d_out);
}